// round 7
// baseline (speedup 1.0000x reference)
#include <cuda_runtime.h>
#include <cuda_bf16.h>
#include <cstdint>
#include <cstddef>

#define SEQ   256
#define BATCH 32
#define NVOC  10000
#define NVPAD 10112     // 79 * 128
#define NH    256
#define NG    1024      // NH * 4 gates
#define MTOT  8192      // SEQ * BATCH
#define NCTA  128
#define CLU   16        // CTAs per cluster
#define NBC   4         // batches per cluster

// ---------------- scratch (static device globals; no allocation) ----------------
__device__ float g_gx[(size_t)MTOT * NG];        // layer-0 gate inputs (32 MB)

// bf16 split buffers for tensor-core decoder
__device__ __nv_bfloat16 g_Ahi[(size_t)MTOT * NH];
__device__ __nv_bfloat16 g_Alo[(size_t)MTOT * NH];
__device__ __nv_bfloat16 g_Whi[(size_t)NVPAD * NH];
__device__ __nv_bfloat16 g_Wlo[(size_t)NVPAD * NH];

// ---------------- gx GEMM (layer 0 only): gx[m][n] = b0[n] + x[m]·Wx0[:,n] ----------------
__global__ __launch_bounds__(256) void gemm_gx(
    const float* __restrict__ embed_W,
    const int*   __restrict__ tokens,
    const float* __restrict__ Wx,      // [256][1024]
    const float* __restrict__ bias)    // [1024]
{
    __shared__ float As[16][132];
    __shared__ float Bs[16][132];

    const int m0 = blockIdx.y * 128;
    const int n0 = blockIdx.x * 128;
    const int t  = threadIdx.x;
    const int tx = t & 15;
    const int ty = t >> 4;

    const int r0 = t >> 2;
    const int r1 = r0 + 64;
    const int kq = (t & 3) * 4;
    const float* ap0 = embed_W + (size_t)tokens[m0 + r0] * NH;
    const float* ap1 = embed_W + (size_t)tokens[m0 + r1] * NH;

    float acc[8][8];
    #pragma unroll
    for (int i = 0; i < 8; i++)
        #pragma unroll
        for (int j = 0; j < 8; j++) acc[i][j] = 0.f;

    for (int k0 = 0; k0 < NH; k0 += 16) {
        {
            float4 v0 = *(const float4*)(ap0 + k0 + kq);
            float4 v1 = *(const float4*)(ap1 + k0 + kq);
            As[kq + 0][r0] = v0.x; As[kq + 1][r0] = v0.y;
            As[kq + 2][r0] = v0.z; As[kq + 3][r0] = v0.w;
            As[kq + 0][r1] = v1.x; As[kq + 1][r1] = v1.y;
            As[kq + 2][r1] = v1.z; As[kq + 3][r1] = v1.w;
        }
        #pragma unroll
        for (int i = 0; i < 2; i++) {
            int lin = t + i * 256;
            int kk  = lin >> 5;
            int nq  = (lin & 31) * 4;
            *(float4*)&Bs[kk][nq] = *(const float4*)(Wx + (size_t)(k0 + kk) * NG + n0 + nq);
        }
        __syncthreads();
        #pragma unroll
        for (int kk = 0; kk < 16; kk++) {
            float a[8], b[8];
            *(float4*)&a[0] = *(const float4*)&As[kk][ty * 8];
            *(float4*)&a[4] = *(const float4*)&As[kk][ty * 8 + 4];
            *(float4*)&b[0] = *(const float4*)&Bs[kk][tx * 8];
            *(float4*)&b[4] = *(const float4*)&Bs[kk][tx * 8 + 4];
            #pragma unroll
            for (int i = 0; i < 8; i++)
                #pragma unroll
                for (int j = 0; j < 8; j++)
                    acc[i][j] += a[i] * b[j];
        }
        __syncthreads();
    }

    #pragma unroll
    for (int i = 0; i < 8; i++) {
        size_t m = (size_t)(m0 + ty * 8 + i);
        float* op = g_gx + m * NG + n0 + tx * 8;
        const float* bp = bias + n0 + tx * 8;
        #pragma unroll
        for (int j = 0; j < 8; j++) op[j] = acc[i][j] + bp[j];
    }
}

// ---------------- fused 2-layer LSTM recurrence (cluster-local exchange) ----------------
// 8 clusters x 16 CTAs x 512 threads. Cluster owns 4 batches; CTA owns 64 gate cols
// (16 cells) with full K. Thread: kh = K-half, b = batch-in-cluster, c = gate col.
// Round r: layer0 step r, layer1 step r-1. h exchanged via DSMEM + cluster.sync.
#define WSTR   260
#define OFF_W0 0
#define OFF_WX (64 * WSTR)
#define OFF_W1 (128 * WSTR)
#define OFF_T  (192 * WSTR)          // tiles: A:h1,h2 then B:h1,h2
#define TILE   (NBC * WSTR)          // 1040 floats
#define OFF_P0 (OFF_T + 4 * TILE)
#define OFF_P1 (OFF_P0 + 512)
#define SMEM_FLOATS (OFF_P1 + 512)
#define SMEM_BYTES  (SMEM_FLOATS * 4)   // 220,416 B

__global__ __launch_bounds__(512, 1) void fused_rnn(
    const float* __restrict__ Wh0,   // [256][1024]
    const float* __restrict__ Wx1,   // [256][1024]
    const float* __restrict__ Wh1,   // [256][1024]
    const float* __restrict__ b1,    // [1024]
    float*       __restrict__ h1_out,
    float*       __restrict__ h2_out)
{
    extern __shared__ float sm[];

    const int t  = threadIdx.x;
    const int kh = t >> 8;                     // K-half
    const int tt = t & 255;
    const int c  = (tt & 7) + ((tt >> 5) << 3);   // 0..63 (8 c x 4 b per warp)
    const int b  = (tt >> 3) & 3;                 // batch within cluster
    uint32_t cc;
    asm("mov.u32 %0, %%cluster_ctarank;" : "=r"(cc));
    const int bg    = (blockIdx.x >> 4) * NBC + b;   // global batch
    const int col0  = (int)cc * 64;
    const bool owner = (tt & 3) == 0;
    const int kg    = (int)cc * 16 + (c >> 2);       // global cell 0..255
    const unsigned lane = t & 31;
    const unsigned base = lane & ~3u;

    // weight slices -> smem (transposed, row per gate col)
    for (int idx = t; idx < 64 * NH; idx += 512) {
        int ccol = idx & 63;
        int j    = idx >> 6;
        sm[OFF_W0 + ccol * WSTR + j] = Wh0[(size_t)j * NG + col0 + ccol];
        sm[OFF_WX + ccol * WSTR + j] = Wx1[(size_t)j * NG + col0 + ccol];
        sm[OFF_W1 + ccol * WSTR + j] = Wh1[(size_t)j * NG + col0 + ccol];
    }
    // zero all 4 h tiles
    for (int idx = t; idx < 4 * TILE; idx += 512) sm[OFF_T + idx] = 0.f;
    const float b1v = b1[col0 + c];

    __syncthreads();
    asm volatile("barrier.cluster.arrive.aligned;" ::: "memory");
    asm volatile("barrier.cluster.wait.aligned;" ::: "memory");

    const uint32_t sb   = (uint32_t)__cvta_generic_to_shared(sm);
    const uint32_t koff = (uint32_t)kh * 512;             // 128 floats
    const uint32_t aw0  = sb + (OFF_W0 + c * WSTR) * 4 + koff;
    const uint32_t awx  = sb + (OFF_WX + c * WSTR) * 4 + koff;
    const uint32_t aw1  = sb + (OFF_W1 + c * WSTR) * 4 + koff;
    const uint32_t ah1A = sb + (OFF_T + b * WSTR) * 4 + koff;
    const uint32_t parD = 2 * TILE * 4;                   // A<->B byte delta

    float c1 = 0.f, c2 = 0.f;

    for (int r = 0; r <= SEQ; r++) {
        // prefetch gx (lower half only)
        float gx0v = 0.f;
        if (t < 256) {
            int s0 = (r < SEQ) ? r : SEQ - 1;
            gx0v = g_gx[(size_t)s0 * BATCH * NG + (size_t)bg * NG + col0 + c];
        }

        const uint32_t pd  = (uint32_t)(r & 1) * parD;
        const uint32_t ah1 = ah1A + pd;
        const uint32_t ah2 = ah1 + TILE * 4;

        // half dot products (f32x2), 32 iterations of 4 K each
        unsigned long long z0a = 0, z0b = 0, zxa = 0, zxb = 0, z2a = 0, z2b = 0;
        #pragma unroll 4
        for (int j = 0; j < 32; j++) {
            int o = j * 16;
            unsigned long long h1a, h1b, h2a, h2b, w0a, w0b, wxa, wxb, w1a, w1b;
            asm volatile("ld.shared.v2.b64 {%0,%1},[%2];" : "=l"(h1a), "=l"(h1b) : "r"(ah1 + o));
            asm volatile("ld.shared.v2.b64 {%0,%1},[%2];" : "=l"(h2a), "=l"(h2b) : "r"(ah2 + o));
            asm volatile("ld.shared.v2.b64 {%0,%1},[%2];" : "=l"(w0a), "=l"(w0b) : "r"(aw0 + o));
            asm volatile("ld.shared.v2.b64 {%0,%1},[%2];" : "=l"(wxa), "=l"(wxb) : "r"(awx + o));
            asm volatile("ld.shared.v2.b64 {%0,%1},[%2];" : "=l"(w1a), "=l"(w1b) : "r"(aw1 + o));
            asm("fma.rn.f32x2 %0,%1,%2,%0;" : "+l"(z0a) : "l"(h1a), "l"(w0a));
            asm("fma.rn.f32x2 %0,%1,%2,%0;" : "+l"(z0b) : "l"(h1b), "l"(w0b));
            asm("fma.rn.f32x2 %0,%1,%2,%0;" : "+l"(zxa) : "l"(h1a), "l"(wxa));
            asm("fma.rn.f32x2 %0,%1,%2,%0;" : "+l"(zxb) : "l"(h1b), "l"(wxb));
            asm("fma.rn.f32x2 %0,%1,%2,%0;" : "+l"(z2a) : "l"(h2a), "l"(w1a));
            asm("fma.rn.f32x2 %0,%1,%2,%0;" : "+l"(z2b) : "l"(h2b), "l"(w1b));
        }

        // partial sums -> smem
        {
            float lo, hi, s0, s1;
            asm("mov.b64 {%0,%1},%2;" : "=f"(lo), "=f"(hi) : "l"(z0a)); s0  = lo + hi;
            asm("mov.b64 {%0,%1},%2;" : "=f"(lo), "=f"(hi) : "l"(z0b)); s0 += lo + hi;
            asm("mov.b64 {%0,%1},%2;" : "=f"(lo), "=f"(hi) : "l"(zxa)); s1  = lo + hi;
            asm("mov.b64 {%0,%1},%2;" : "=f"(lo), "=f"(hi) : "l"(zxb)); s1 += lo + hi;
            asm("mov.b64 {%0,%1},%2;" : "=f"(lo), "=f"(hi) : "l"(z2a)); s1 += lo + hi;
            asm("mov.b64 {%0,%1},%2;" : "=f"(lo), "=f"(hi) : "l"(z2b)); s1 += lo + hi;
            sm[OFF_P0 + t] = s0;
            sm[OFF_P1 + t] = s1;
        }
        __syncthreads();

        if (t < 256) {
            float z0 = gx0v + sm[OFF_P0 + t] + sm[OFF_P0 + t + 256];
            float z1 = b1v  + sm[OFF_P1 + t] + sm[OFF_P1 + t + 256];

            float zi0 = __shfl_sync(0xffffffffu, z0, base + 0);
            float zf0 = __shfl_sync(0xffffffffu, z0, base + 1);
            float zo0 = __shfl_sync(0xffffffffu, z0, base + 2);
            float zg0 = __shfl_sync(0xffffffffu, z0, base + 3);
            float zi1 = __shfl_sync(0xffffffffu, z1, base + 0);
            float zf1 = __shfl_sync(0xffffffffu, z1, base + 1);
            float zo1 = __shfl_sync(0xffffffffu, z1, base + 2);
            float zg1 = __shfl_sync(0xffffffffu, z1, base + 3);

            if (owner) {
                const uint32_t npd = (uint32_t)((r & 1) ^ 1) * parD;
                const uint32_t l1  = sb + (uint32_t)(OFF_T + b * WSTR + kg) * 4 + npd;
                const uint32_t l2  = l1 + TILE * 4;
                float hn1 = 0.f, hn2 = 0.f;

                if (r < SEQ) {      // layer 0 step r
                    float ig = 1.f / (1.f + __expf(-zi0));
                    float fg = 1.f / (1.f + __expf(-zf0));
                    float og = 1.f / (1.f + __expf(-zo0));
                    float gg = tanhf(zg0);
                    c1  = fg * c1 + ig * gg;
                    hn1 = og * tanhf(c1);
                    if (r == SEQ - 1) h1_out[bg * NH + kg] = hn1;
                }
                if (r >= 1) {       // layer 1 step r-1
                    int s1i = r - 1;
                    float ig = 1.f / (1.f + __expf(-zi1));
                    float fg = 1.f / (1.f + __expf(-zf1));
                    float og = 1.f / (1.f + __expf(-zo1));
                    float gg = tanhf(zg1);
                    c2  = fg * c2 + ig * gg;
                    hn2 = og * tanhf(c2);
                    size_t m = (size_t)s1i * BATCH + bg;
                    __nv_bfloat16 hb = __float2bfloat16_rn(hn2);
                    g_Ahi[m * NH + kg] = hb;
                    g_Alo[m * NH + kg] = __float2bfloat16_rn(hn2 - __bfloat162float(hb));
                    if (s1i == SEQ - 1) h2_out[bg * NH + kg] = hn2;
                }

                // publish h to every cluster CTA's next tiles (DSMEM)
                #pragma unroll 4
                for (int rk = 0; rk < CLU; rk++) {
                    uint32_t a1, a2;
                    asm("mapa.shared::cluster.u32 %0,%1,%2;" : "=r"(a1) : "r"(l1), "r"(rk));
                    asm("mapa.shared::cluster.u32 %0,%1,%2;" : "=r"(a2) : "r"(l2), "r"(rk));
                    if (r < SEQ)
                        asm volatile("st.shared::cluster.f32 [%0],%1;" :: "r"(a1), "f"(hn1) : "memory");
                    if (r >= 1)
                        asm volatile("st.shared::cluster.f32 [%0],%1;" :: "r"(a2), "f"(hn2) : "memory");
                }
            }
        }

        // round barrier: release own DSMEM stores, acquire peers'
        if (r < SEQ) {
            asm volatile("barrier.cluster.arrive.aligned;" ::: "memory");
            asm volatile("barrier.cluster.wait.aligned;" ::: "memory");
        }
    }
}

// ---------------- bf16 split of decoder weights ----------------
__global__ __launch_bounds__(256) void conv_W(const float* __restrict__ W) {
    int i = blockIdx.x * blockDim.x + threadIdx.x;
    if (i < NVPAD * NH) {
        int v = i >> 8;
        float x = (v < NVOC) ? W[(size_t)v * NH + (i & 255)] : 0.f;
        __nv_bfloat16 hi = __float2bfloat16_rn(x);
        g_Whi[i] = hi;
        g_Wlo[i] = __float2bfloat16_rn(x - __bfloat162float(hi));
    }
}

// ---------------- tensor-core decoder GEMM (split-bf16, 3 products) ----------------
#define LDM_A(r0,r1,r2,r3,addr) \
    asm volatile("ldmatrix.sync.aligned.m8n8.x4.shared.b16 {%0,%1,%2,%3}, [%4];" \
        : "=r"(r0), "=r"(r1), "=r"(r2), "=r"(r3) : "r"(addr))

#define MMA_BF16(c, a, b) \
    asm volatile("mma.sync.aligned.m16n8k16.row.col.f32.bf16.bf16.f32 " \
        "{%0,%1,%2,%3}, {%4,%5,%6,%7}, {%8,%9}, {%0,%1,%2,%3};" \
        : "+f"((c)[0]), "+f"((c)[1]), "+f"((c)[2]), "+f"((c)[3]) \
        : "r"((a)[0]), "r"((a)[1]), "r"((a)[2]), "r"((a)[3]), "r"((b)[0]), "r"((b)[1]))

__global__ __launch_bounds__(256) void gemm_dec_tc(
    const float* __restrict__ bias,
    float*       __restrict__ out)
{
    __shared__ __nv_bfloat16 sAhi[128][40];
    __shared__ __nv_bfloat16 sAlo[128][40];
    __shared__ __nv_bfloat16 sBhi[128][40];
    __shared__ __nv_bfloat16 sBlo[128][40];

    const int t    = threadIdx.x;
    const int warp = t >> 5;
    const int lane = t & 31;
    const int m0   = blockIdx.y * 128;
    const int n0   = blockIdx.x * 128;
    const int wm   = warp >> 2;
    const int wn   = warp & 3;

    float acc[4][4][4];
    #pragma unroll
    for (int i = 0; i < 4; i++)
        #pragma unroll
        for (int j = 0; j < 4; j++)
            #pragma unroll
            for (int q = 0; q < 4; q++) acc[i][j][q] = 0.f;

    const uint32_t bAhi = (uint32_t)__cvta_generic_to_shared(&sAhi[0][0]);
    const uint32_t bAlo = (uint32_t)__cvta_generic_to_shared(&sAlo[0][0]);
    const uint32_t bBhi = (uint32_t)__cvta_generic_to_shared(&sBhi[0][0]);
    const uint32_t bBlo = (uint32_t)__cvta_generic_to_shared(&sBlo[0][0]);

    const int a_row = (lane & 15);
    const int a_k   = (lane >> 4) * 8;
    const int b_row = (lane & 7) + ((lane >> 4) << 3);
    const int b_k   = ((lane >> 3) & 1) * 8;

    for (int kc = 0; kc < 8; kc++) {
        const int k0 = kc * 32;
        #pragma unroll
        for (int h = 0; h < 2; h++) {
            int cc  = t + h * 256;
            int row = cc >> 2;
            int q   = cc & 3;
            size_t gA = (size_t)(m0 + row) * NH + k0 + q * 8;
            size_t gB = (size_t)(n0 + row) * NH + k0 + q * 8;
            *(uint4*)&sAhi[row][q * 8] = *(const uint4*)(g_Ahi + gA);
            *(uint4*)&sAlo[row][q * 8] = *(const uint4*)(g_Alo + gA);
            *(uint4*)&sBhi[row][q * 8] = *(const uint4*)(g_Whi + gB);
            *(uint4*)&sBlo[row][q * 8] = *(const uint4*)(g_Wlo + gB);
        }
        __syncthreads();

        #pragma unroll
        for (int ks = 0; ks < 32; ks += 16) {
            uint32_t af[4][4];
            uint32_t bh[4][2], bl[4][2];

            #pragma unroll
            for (int nh = 0; nh < 2; nh++) {
                int roff = (wn * 32 + nh * 16 + b_row) * 40 + ks + b_k;
                uint32_t r0, r1, r2, r3;
                LDM_A(r0, r1, r2, r3, bBhi + roff * 2);
                bh[2*nh][0] = r0; bh[2*nh][1] = r1;
                bh[2*nh+1][0] = r2; bh[2*nh+1][1] = r3;
                LDM_A(r0, r1, r2, r3, bBlo + roff * 2);
                bl[2*nh][0] = r0; bl[2*nh][1] = r1;
                bl[2*nh+1][0] = r2; bl[2*nh+1][1] = r3;
            }

            #pragma unroll
            for (int mi = 0; mi < 4; mi++) {
                int roff = (wm * 64 + mi * 16 + a_row) * 40 + ks + a_k;
                LDM_A(af[mi][0], af[mi][1], af[mi][2], af[mi][3], bAhi + roff * 2);
            }
            #pragma unroll
            for (int mi = 0; mi < 4; mi++)
                #pragma unroll
                for (int ni = 0; ni < 4; ni++) {
                    MMA_BF16(acc[mi][ni], af[mi], bh[ni]);
                    MMA_BF16(acc[mi][ni], af[mi], bl[ni]);
                }
            #pragma unroll
            for (int mi = 0; mi < 4; mi++) {
                int roff = (wm * 64 + mi * 16 + a_row) * 40 + ks + a_k;
                LDM_A(af[mi][0], af[mi][1], af[mi][2], af[mi][3], bAlo + roff * 2);
            }
            #pragma unroll
            for (int mi = 0; mi < 4; mi++)
                #pragma unroll
                for (int ni = 0; ni < 4; ni++)
                    MMA_BF16(acc[mi][ni], af[mi], bh[ni]);
        }
        __syncthreads();
    }

    const int g  = lane >> 2;
    const int t4 = lane & 3;
    #pragma unroll
    for (int mi = 0; mi < 4; mi++) {
        #pragma unroll
        for (int ni = 0; ni < 4; ni++) {
            int col = n0 + wn * 32 + ni * 8 + t4 * 2;
            if (col < NVOC) {
                float b0 = bias[col], b1 = bias[col + 1];
                int row0 = m0 + wm * 64 + mi * 16 + g;
                float2 v0 = make_float2(acc[mi][ni][0] + b0, acc[mi][ni][1] + b1);
                float2 v1 = make_float2(acc[mi][ni][2] + b0, acc[mi][ni][3] + b1);
                *(float2*)(out + (size_t)row0 * NVOC + col) = v0;
                *(float2*)(out + (size_t)(row0 + 8) * NVOC + col) = v1;
            }
        }
    }
}

// ---------------- launch ----------------
extern "C" void kernel_launch(void* const* d_in, const int* in_sizes, int n_in,
                              void* d_out, int out_size) {
    const int*   tokens  = (const int*)  d_in[0];
    const float* embed_W = (const float*)d_in[1];
    const float* Wx0     = (const float*)d_in[2];
    const float* Wh0     = (const float*)d_in[3];
    const float* b0      = (const float*)d_in[4];
    const float* Wx1     = (const float*)d_in[5];
    const float* Wh1     = (const float*)d_in[6];
    const float* b1      = (const float*)d_in[7];
    const float* dec_W   = (const float*)d_in[8];
    const float* dec_b   = (const float*)d_in[9];
    (void)in_sizes; (void)n_in;

    float* out    = (float*)d_out;
    float* h1_out = out + (size_t)out_size - 2 * BATCH * NH;
    float* h2_out = out + (size_t)out_size - 1 * BATCH * NH;

    static bool attr_done = false;
    if (!attr_done) {
        cudaFuncSetAttribute(fused_rnn, cudaFuncAttributeMaxDynamicSharedMemorySize, SMEM_BYTES);
        cudaFuncSetAttribute(fused_rnn, cudaFuncAttributeNonPortableClusterSizeAllowed, 1);
        attr_done = true;
    }

    conv_W<<<(NVPAD * NH + 255) / 256, 256>>>(dec_W);
    gemm_gx<<<dim3(8, 64), 256>>>(embed_W, tokens, Wx0, b0);

    cudaLaunchConfig_t cfg = {};
    cfg.gridDim  = dim3(NCTA, 1, 1);
    cfg.blockDim = dim3(512, 1, 1);
    cfg.dynamicSmemBytes = SMEM_BYTES;
    cfg.stream = 0;
    cudaLaunchAttribute attrs[1];
    attrs[0].id = cudaLaunchAttributeClusterDimension;
    attrs[0].val.clusterDim.x = CLU;
    attrs[0].val.clusterDim.y = 1;
    attrs[0].val.clusterDim.z = 1;
    cfg.attrs = attrs;
    cfg.numAttrs = 1;
    cudaLaunchKernelEx(&cfg, fused_rnn, Wh0, Wx1, Wh1, b1, h1_out, h2_out);

    gemm_dec_tc<<<dim3(79, 64), 256>>>(dec_b, out);
}

// round 9
// speedup vs baseline: 1.5856x; 1.5856x over previous
#include <cuda_runtime.h>
#include <cuda_bf16.h>
#include <cstdint>
#include <cstddef>

#define SEQ   256
#define BATCH 32
#define NVOC  10000
#define NVPAD 10112     // 79 * 128
#define NH    256
#define NG    1024      // NH * 4 gates
#define MTOT  8192      // SEQ * BATCH

// ---------------- scratch (static device globals; no allocation) ----------------
__device__ float    g_gx[(size_t)MTOT * NG];     // layer-0 gate inputs (32 MB)
__device__ float    g_h1buf[2][BATCH * NH];      // layer-0 h ping-pong
__device__ float    g_h2buf[2][BATCH * NH];      // layer-1 h ping-pong
__device__ unsigned g_cnt;                       // barrier arrival counter
__device__ unsigned g_flag;                      // release flag

// bf16 split buffers for tensor-core decoder
__device__ __nv_bfloat16 g_Ahi[(size_t)MTOT * NH];
__device__ __nv_bfloat16 g_Alo[(size_t)MTOT * NH];
__device__ __nv_bfloat16 g_Whi[(size_t)NVPAD * NH];
__device__ __nv_bfloat16 g_Wlo[(size_t)NVPAD * NH];

// ---------------- init: zero h state + barrier ----------------
__global__ void init_state() {
    int t = blockIdx.x * blockDim.x + threadIdx.x;
    int nthr = gridDim.x * blockDim.x;
    for (int i = t; i < 2 * BATCH * NH; i += nthr) {
        ((float*)g_h1buf)[i] = 0.f;
        ((float*)g_h2buf)[i] = 0.f;
    }
    if (t == 0) { g_cnt = 0u; g_flag = 0u; }
}

// ---------------- gx GEMM (layer 0 only, fp32 — proven): ----------------
__global__ __launch_bounds__(256) void gemm_gx(
    const float* __restrict__ embed_W,
    const int*   __restrict__ tokens,
    const float* __restrict__ Wx,      // [256][1024]
    const float* __restrict__ bias)    // [1024]
{
    __shared__ float As[16][132];
    __shared__ float Bs[16][132];

    const int m0 = blockIdx.y * 128;
    const int n0 = blockIdx.x * 128;
    const int t  = threadIdx.x;
    const int tx = t & 15;
    const int ty = t >> 4;

    const int r0 = t >> 2;
    const int r1 = r0 + 64;
    const int kq = (t & 3) * 4;
    const float* ap0 = embed_W + (size_t)tokens[m0 + r0] * NH;
    const float* ap1 = embed_W + (size_t)tokens[m0 + r1] * NH;

    float acc[8][8];
    #pragma unroll
    for (int i = 0; i < 8; i++)
        #pragma unroll
        for (int j = 0; j < 8; j++) acc[i][j] = 0.f;

    for (int k0 = 0; k0 < NH; k0 += 16) {
        {
            float4 v0 = *(const float4*)(ap0 + k0 + kq);
            float4 v1 = *(const float4*)(ap1 + k0 + kq);
            As[kq + 0][r0] = v0.x; As[kq + 1][r0] = v0.y;
            As[kq + 2][r0] = v0.z; As[kq + 3][r0] = v0.w;
            As[kq + 0][r1] = v1.x; As[kq + 1][r1] = v1.y;
            As[kq + 2][r1] = v1.z; As[kq + 3][r1] = v1.w;
        }
        #pragma unroll
        for (int i = 0; i < 2; i++) {
            int lin = t + i * 256;
            int kk  = lin >> 5;
            int nq  = (lin & 31) * 4;
            *(float4*)&Bs[kk][nq] = *(const float4*)(Wx + (size_t)(k0 + kk) * NG + n0 + nq);
        }
        __syncthreads();
        #pragma unroll
        for (int kk = 0; kk < 16; kk++) {
            float a[8], b[8];
            *(float4*)&a[0] = *(const float4*)&As[kk][ty * 8];
            *(float4*)&a[4] = *(const float4*)&As[kk][ty * 8 + 4];
            *(float4*)&b[0] = *(const float4*)&Bs[kk][tx * 8];
            *(float4*)&b[4] = *(const float4*)&Bs[kk][tx * 8 + 4];
            #pragma unroll
            for (int i = 0; i < 8; i++)
                #pragma unroll
                for (int j = 0; j < 8; j++)
                    acc[i][j] += a[i] * b[j];
        }
        __syncthreads();
    }

    #pragma unroll
    for (int i = 0; i < 8; i++) {
        size_t m = (size_t)(m0 + ty * 8 + i);
        float* op = g_gx + m * NG + n0 + tx * 8;
        const float* bp = bias + n0 + tx * 8;
        #pragma unroll
        for (int j = 0; j < 8; j++) op[j] = acc[i][j] + bp[j];
    }
}

// ---------------- fused 2-layer LSTM recurrence (round-4 kernel, best measured) ----------------
#define WSTR   260
#define OFF_W0 0
#define OFF_WX (8  * WSTR)
#define OFF_W1 (16 * WSTR)
#define OFF_H1 (24 * WSTR)
#define OFF_H2 (56 * WSTR)
#define SMEM_FLOATS (88 * WSTR)
#define SMEM_BYTES  (SMEM_FLOATS * 4)

__global__ __launch_bounds__(256, 1) void fused_rnn(
    const float* __restrict__ Wh0,
    const float* __restrict__ Wx1,
    const float* __restrict__ Wh1,
    const float* __restrict__ b1,
    float*       __restrict__ h1_out,
    float*       __restrict__ h2_out)
{
    extern __shared__ float sm[];

    const int t   = threadIdx.x;
    const int kg0 = blockIdx.x * 8;
    const int c   = t & 7;
    const int b   = t >> 3;
    const int k   = (kg0 + c) >> 2;
    const bool owner = (t & 3) == 0;
    const unsigned lane = t & 31;
    const unsigned base = lane & ~3u;
    const unsigned grid = gridDim.x;

    for (int idx = t; idx < 8 * NH; idx += 256) {
        int j = idx >> 3, cc = idx & 7;
        sm[OFF_W0 + cc * WSTR + j] = Wh0[(size_t)j * NG + kg0 + cc];
        sm[OFF_WX + cc * WSTR + j] = Wx1[(size_t)j * NG + kg0 + cc];
        sm[OFF_W1 + cc * WSTR + j] = Wh1[(size_t)j * NG + kg0 + cc];
    }
    const float b1v = b1[kg0 + c];

    const uint32_t sb  = (uint32_t)__cvta_generic_to_shared(sm);
    const uint32_t ah1 = sb + (OFF_H1 + b * WSTR) * 4;
    const uint32_t ah2 = sb + (OFF_H2 + b * WSTR) * 4;
    const uint32_t aw0 = sb + (OFF_W0 + c * WSTR) * 4;
    const uint32_t awx = sb + (OFF_WX + c * WSTR) * 4;
    const uint32_t aw1 = sb + (OFF_W1 + c * WSTR) * 4;

    float c1 = 0.f, c2 = 0.f;

    for (int r = 0; r <= SEQ; r++) {
        int s0 = (r < SEQ) ? r : SEQ - 1;
        float gx0v = g_gx[(size_t)s0 * BATCH * NG + (size_t)b * NG + kg0 + c];

        if (r > 0 && t == 0) {
            while (*(volatile unsigned*)&g_flag < (unsigned)r) { }
            __threadfence();
        }
        __syncthreads();

        {
            const float4* s1p = (const float4*)g_h1buf[r & 1];
            const float4* s2p = (const float4*)g_h2buf[r & 1];
            #pragma unroll
            for (int i = 0; i < 8; i++) {
                int idx = t + i * 256;
                int bb = idx >> 6, jj = (idx & 63) * 4;
                *(float4*)&sm[OFF_H1 + bb * WSTR + jj] = __ldcg(s1p + idx);
                *(float4*)&sm[OFF_H2 + bb * WSTR + jj] = __ldcg(s2p + idx);
            }
        }
        __syncthreads();

        unsigned long long z0a = 0, z0b = 0, zxa = 0, zxb = 0, z2a = 0, z2b = 0;
        #pragma unroll 8
        for (int j = 0; j < 64; j++) {
            int o = j * 16;
            unsigned long long h1a, h1b, h2a, h2b, w0a, w0b, wxa, wxb, w1a, w1b;
            asm volatile("ld.shared.v2.b64 {%0,%1},[%2];" : "=l"(h1a), "=l"(h1b) : "r"(ah1 + o));
            asm volatile("ld.shared.v2.b64 {%0,%1},[%2];" : "=l"(h2a), "=l"(h2b) : "r"(ah2 + o));
            asm volatile("ld.shared.v2.b64 {%0,%1},[%2];" : "=l"(w0a), "=l"(w0b) : "r"(aw0 + o));
            asm volatile("ld.shared.v2.b64 {%0,%1},[%2];" : "=l"(wxa), "=l"(wxb) : "r"(awx + o));
            asm volatile("ld.shared.v2.b64 {%0,%1},[%2];" : "=l"(w1a), "=l"(w1b) : "r"(aw1 + o));
            asm("fma.rn.f32x2 %0,%1,%2,%0;" : "+l"(z0a) : "l"(h1a), "l"(w0a));
            asm("fma.rn.f32x2 %0,%1,%2,%0;" : "+l"(z0b) : "l"(h1b), "l"(w0b));
            asm("fma.rn.f32x2 %0,%1,%2,%0;" : "+l"(zxa) : "l"(h1a), "l"(wxa));
            asm("fma.rn.f32x2 %0,%1,%2,%0;" : "+l"(zxb) : "l"(h1b), "l"(wxb));
            asm("fma.rn.f32x2 %0,%1,%2,%0;" : "+l"(z2a) : "l"(h2a), "l"(w1a));
            asm("fma.rn.f32x2 %0,%1,%2,%0;" : "+l"(z2b) : "l"(h2b), "l"(w1b));
        }

        float z0, z1;
        {
            float lo, hi, s;
            asm("mov.b64 {%0,%1},%2;" : "=f"(lo), "=f"(hi) : "l"(z0a)); s  = lo + hi;
            asm("mov.b64 {%0,%1},%2;" : "=f"(lo), "=f"(hi) : "l"(z0b)); s += lo + hi;
            z0 = gx0v + s;
            asm("mov.b64 {%0,%1},%2;" : "=f"(lo), "=f"(hi) : "l"(zxa)); s  = lo + hi;
            asm("mov.b64 {%0,%1},%2;" : "=f"(lo), "=f"(hi) : "l"(zxb)); s += lo + hi;
            asm("mov.b64 {%0,%1},%2;" : "=f"(lo), "=f"(hi) : "l"(z2a)); s += lo + hi;
            asm("mov.b64 {%0,%1},%2;" : "=f"(lo), "=f"(hi) : "l"(z2b)); s += lo + hi;
            z1 = b1v + s;
        }

        float zi0 = __shfl_sync(0xffffffffu, z0, base + 0);
        float zf0 = __shfl_sync(0xffffffffu, z0, base + 1);
        float zo0 = __shfl_sync(0xffffffffu, z0, base + 2);
        float zg0 = __shfl_sync(0xffffffffu, z0, base + 3);
        float zi1 = __shfl_sync(0xffffffffu, z1, base + 0);
        float zf1 = __shfl_sync(0xffffffffu, z1, base + 1);
        float zo1 = __shfl_sync(0xffffffffu, z1, base + 2);
        float zg1 = __shfl_sync(0xffffffffu, z1, base + 3);

        if (owner) {
            if (r < SEQ) {
                float ig = 1.f / (1.f + __expf(-zi0));
                float fg = 1.f / (1.f + __expf(-zf0));
                float og = 1.f / (1.f + __expf(-zo0));
                float gg = tanhf(zg0);
                c1 = fg * c1 + ig * gg;
                float hn = og * tanhf(c1);
                g_h1buf[(r + 1) & 1][b * NH + k] = hn;
                if (r == SEQ - 1) h1_out[b * NH + k] = hn;
            }
            if (r >= 1) {
                int s1 = r - 1;
                float ig = 1.f / (1.f + __expf(-zi1));
                float fg = 1.f / (1.f + __expf(-zf1));
                float og = 1.f / (1.f + __expf(-zo1));
                float gg = tanhf(zg1);
                c2 = fg * c2 + ig * gg;
                float hn = og * tanhf(c2);
                g_h2buf[(r + 1) & 1][b * NH + k] = hn;
                size_t m = (size_t)s1 * BATCH + b;
                __nv_bfloat16 hb = __float2bfloat16_rn(hn);
                g_Ahi[m * NH + k] = hb;
                g_Alo[m * NH + k] = __float2bfloat16_rn(hn - __bfloat162float(hb));
                if (s1 == SEQ - 1) h2_out[b * NH + k] = hn;
            }
        }

        if (r < SEQ) {
            __syncthreads();
            if (t == 0) {
                __threadfence();
                unsigned old = atomicAdd(&g_cnt, 1u);
                if (old == (unsigned)r * grid + grid - 1u)
                    atomicExch(&g_flag, (unsigned)(r + 1));
            }
        }
    }
}

// ---------------- bf16 split of decoder weights (scalar — proven) ----------------
__global__ __launch_bounds__(256) void conv_W(const float* __restrict__ W) {
    int i = blockIdx.x * blockDim.x + threadIdx.x;
    if (i < NVPAD * NH) {
        int v = i >> 8;
        float x = (v < NVOC) ? W[(size_t)v * NH + (i & 255)] : 0.f;
        __nv_bfloat16 hi = __float2bfloat16_rn(x);
        g_Whi[i] = hi;
        g_Wlo[i] = __float2bfloat16_rn(x - __bfloat162float(hi));
    }
}

// ---------------- tensor-core decoder GEMM (split-bf16, 3 products; 2 CTAs/SM) ----------------
#define LDM_A(r0,r1,r2,r3,addr) \
    asm volatile("ldmatrix.sync.aligned.m8n8.x4.shared.b16 {%0,%1,%2,%3}, [%4];" \
        : "=r"(r0), "=r"(r1), "=r"(r2), "=r"(r3) : "r"(addr))

#define MMA_BF16(c, a, b) \
    asm volatile("mma.sync.aligned.m16n8k16.row.col.f32.bf16.bf16.f32 " \
        "{%0,%1,%2,%3}, {%4,%5,%6,%7}, {%8,%9}, {%0,%1,%2,%3};" \
        : "+f"((c)[0]), "+f"((c)[1]), "+f"((c)[2]), "+f"((c)[3]) \
        : "r"((a)[0]), "r"((a)[1]), "r"((a)[2]), "r"((a)[3]), "r"((b)[0]), "r"((b)[1]))

__global__ __launch_bounds__(256, 2) void gemm_dec_tc(
    const float* __restrict__ bias,
    float*       __restrict__ out)
{
    __shared__ __nv_bfloat16 sAhi[128][40];
    __shared__ __nv_bfloat16 sAlo[128][40];
    __shared__ __nv_bfloat16 sBhi[128][40];
    __shared__ __nv_bfloat16 sBlo[128][40];

    const int t    = threadIdx.x;
    const int warp = t >> 5;
    const int lane = t & 31;
    const int m0   = blockIdx.y * 128;
    const int n0   = blockIdx.x * 128;
    const int wm   = warp >> 2;
    const int wn   = warp & 3;

    float acc[4][4][4];
    #pragma unroll
    for (int i = 0; i < 4; i++)
        #pragma unroll
        for (int j = 0; j < 4; j++)
            #pragma unroll
            for (int q = 0; q < 4; q++) acc[i][j][q] = 0.f;

    const uint32_t bAhi = (uint32_t)__cvta_generic_to_shared(&sAhi[0][0]);
    const uint32_t bAlo = (uint32_t)__cvta_generic_to_shared(&sAlo[0][0]);
    const uint32_t bBhi = (uint32_t)__cvta_generic_to_shared(&sBhi[0][0]);
    const uint32_t bBlo = (uint32_t)__cvta_generic_to_shared(&sBlo[0][0]);

    const int a_row = (lane & 15);
    const int a_k   = (lane >> 4) * 8;
    const int b_row = (lane & 7) + ((lane >> 4) << 3);
    const int b_k   = ((lane >> 3) & 1) * 8;

    for (int kc = 0; kc < 8; kc++) {
        const int k0 = kc * 32;
        #pragma unroll
        for (int h = 0; h < 2; h++) {
            int cc  = t + h * 256;
            int row = cc >> 2;
            int q   = cc & 3;
            size_t gA = (size_t)(m0 + row) * NH + k0 + q * 8;
            size_t gB = (size_t)(n0 + row) * NH + k0 + q * 8;
            *(uint4*)&sAhi[row][q * 8] = *(const uint4*)(g_Ahi + gA);
            *(uint4*)&sAlo[row][q * 8] = *(const uint4*)(g_Alo + gA);
            *(uint4*)&sBhi[row][q * 8] = *(const uint4*)(g_Whi + gB);
            *(uint4*)&sBlo[row][q * 8] = *(const uint4*)(g_Wlo + gB);
        }
        __syncthreads();

        #pragma unroll
        for (int ks = 0; ks < 32; ks += 16) {
            uint32_t af[4][4];
            uint32_t bh[4][2], bl[4][2];

            #pragma unroll
            for (int nh = 0; nh < 2; nh++) {
                int roff = (wn * 32 + nh * 16 + b_row) * 40 + ks + b_k;
                uint32_t r0, r1, r2, r3;
                LDM_A(r0, r1, r2, r3, bBhi + roff * 2);
                bh[2*nh][0] = r0; bh[2*nh][1] = r1;
                bh[2*nh+1][0] = r2; bh[2*nh+1][1] = r3;
                LDM_A(r0, r1, r2, r3, bBlo + roff * 2);
                bl[2*nh][0] = r0; bl[2*nh][1] = r1;
                bl[2*nh+1][0] = r2; bl[2*nh+1][1] = r3;
            }
            #pragma unroll
            for (int mi = 0; mi < 4; mi++) {
                int roff = (wm * 64 + mi * 16 + a_row) * 40 + ks + a_k;
                LDM_A(af[mi][0], af[mi][1], af[mi][2], af[mi][3], bAhi + roff * 2);
            }
            #pragma unroll
            for (int mi = 0; mi < 4; mi++)
                #pragma unroll
                for (int ni = 0; ni < 4; ni++) {
                    MMA_BF16(acc[mi][ni], af[mi], bh[ni]);
                    MMA_BF16(acc[mi][ni], af[mi], bl[ni]);
                }
            #pragma unroll
            for (int mi = 0; mi < 4; mi++) {
                int roff = (wm * 64 + mi * 16 + a_row) * 40 + ks + a_k;
                LDM_A(af[mi][0], af[mi][1], af[mi][2], af[mi][3], bAlo + roff * 2);
            }
            #pragma unroll
            for (int mi = 0; mi < 4; mi++)
                #pragma unroll
                for (int ni = 0; ni < 4; ni++)
                    MMA_BF16(acc[mi][ni], af[mi], bh[ni]);
        }
        __syncthreads();
    }

    const int g  = lane >> 2;
    const int t4 = lane & 3;
    #pragma unroll
    for (int mi = 0; mi < 4; mi++) {
        #pragma unroll
        for (int ni = 0; ni < 4; ni++) {
            int col = n0 + wn * 32 + ni * 8 + t4 * 2;
            if (col < NVOC) {
                float b0 = bias[col], b1 = bias[col + 1];
                int row0 = m0 + wm * 64 + mi * 16 + g;
                float2 v0 = make_float2(acc[mi][ni][0] + b0, acc[mi][ni][1] + b1);
                float2 v1 = make_float2(acc[mi][ni][2] + b0, acc[mi][ni][3] + b1);
                *(float2*)(out + (size_t)row0 * NVOC + col) = v0;
                *(float2*)(out + (size_t)(row0 + 8) * NVOC + col) = v1;
            }
        }
    }
}

// ---------------- launch ----------------
extern "C" void kernel_launch(void* const* d_in, const int* in_sizes, int n_in,
                              void* d_out, int out_size) {
    const int*   tokens  = (const int*)  d_in[0];
    const float* embed_W = (const float*)d_in[1];
    const float* Wx0     = (const float*)d_in[2];
    const float* Wh0     = (const float*)d_in[3];
    const float* b0      = (const float*)d_in[4];
    const float* Wx1     = (const float*)d_in[5];
    const float* Wh1     = (const float*)d_in[6];
    const float* b1      = (const float*)d_in[7];
    const float* dec_W   = (const float*)d_in[8];
    const float* dec_b   = (const float*)d_in[9];
    (void)in_sizes; (void)n_in;

    float* out    = (float*)d_out;
    float* h1_out = out + (size_t)out_size - 2 * BATCH * NH;
    float* h2_out = out + (size_t)out_size - 1 * BATCH * NH;

    static bool attr_done = false;
    if (!attr_done) {
        cudaFuncSetAttribute(fused_rnn, cudaFuncAttributeMaxDynamicSharedMemorySize, SMEM_BYTES);
        attr_done = true;
    }

    conv_W<<<(NVPAD * NH + 255) / 256, 256>>>(dec_W);
    init_state<<<16, 256>>>();
    gemm_gx<<<dim3(8, 64), 256>>>(embed_W, tokens, Wx0, b0);
    fused_rnn<<<128, 256, SMEM_BYTES>>>(Wh0, Wx1, Wh1, b1, h1_out, h2_out);
    gemm_dec_tc<<<dim3(79, 64), 256>>>(dec_b, out);
}

// round 10
// speedup vs baseline: 2.0669x; 1.3036x over previous
#include <cuda_runtime.h>
#include <cuda_bf16.h>
#include <cstdint>
#include <cstddef>

#define SEQ   256
#define BATCH 32
#define NVOC  10000
#define NVPAD 10112     // 79 * 128
#define NH    256
#define NG    1024      // NH * 4 gates
#define MTOT  8192      // SEQ * BATCH

// ---------------- scratch (static device globals; no allocation) ----------------
__device__ float    g_gx[(size_t)MTOT * NG];     // layer-0 gate inputs (32 MB)
__device__ unsigned g_cnt;                       // barrier arrival counter
__device__ unsigned g_flag;                      // release flag

// h exchange planes (bf16 hi/lo split, ping-pong parity)
__device__ __nv_bfloat16 g_h1hi[2][BATCH * NH];
__device__ __nv_bfloat16 g_h1lo[2][BATCH * NH];
__device__ __nv_bfloat16 g_h2hi[2][BATCH * NH];
__device__ __nv_bfloat16 g_h2lo[2][BATCH * NH];

// bf16 split buffers for tensor-core decoder
__device__ __nv_bfloat16 g_Ahi[(size_t)MTOT * NH];
__device__ __nv_bfloat16 g_Alo[(size_t)MTOT * NH];
__device__ __nv_bfloat16 g_Whi[(size_t)NVPAD * NH];
__device__ __nv_bfloat16 g_Wlo[(size_t)NVPAD * NH];

// ---------------- init: zero h planes + barrier ----------------
__global__ void init_state() {
    int t = blockIdx.x * blockDim.x + threadIdx.x;
    int nthr = gridDim.x * blockDim.x;
    // 4 plane-pairs x 2 parity x 8192 bf16 = 32768 uint32 words
    uint32_t* p1h = (uint32_t*)g_h1hi; uint32_t* p1l = (uint32_t*)g_h1lo;
    uint32_t* p2h = (uint32_t*)g_h2hi; uint32_t* p2l = (uint32_t*)g_h2lo;
    for (int i = t; i < 2 * BATCH * NH / 2; i += nthr) {
        p1h[i] = 0u; p1l[i] = 0u; p2h[i] = 0u; p2l[i] = 0u;
    }
    if (t == 0) { g_cnt = 0u; g_flag = 0u; }
}

// ---------------- gx GEMM (layer 0 only, fp32 — proven) ----------------
__global__ __launch_bounds__(256) void gemm_gx(
    const float* __restrict__ embed_W,
    const int*   __restrict__ tokens,
    const float* __restrict__ Wx,      // [256][1024]
    const float* __restrict__ bias)    // [1024]
{
    __shared__ float As[16][132];
    __shared__ float Bs[16][132];

    const int m0 = blockIdx.y * 128;
    const int n0 = blockIdx.x * 128;
    const int t  = threadIdx.x;
    const int tx = t & 15;
    const int ty = t >> 4;

    const int r0 = t >> 2;
    const int r1 = r0 + 64;
    const int kq = (t & 3) * 4;
    const float* ap0 = embed_W + (size_t)tokens[m0 + r0] * NH;
    const float* ap1 = embed_W + (size_t)tokens[m0 + r1] * NH;

    float acc[8][8];
    #pragma unroll
    for (int i = 0; i < 8; i++)
        #pragma unroll
        for (int j = 0; j < 8; j++) acc[i][j] = 0.f;

    for (int k0 = 0; k0 < NH; k0 += 16) {
        {
            float4 v0 = *(const float4*)(ap0 + k0 + kq);
            float4 v1 = *(const float4*)(ap1 + k0 + kq);
            As[kq + 0][r0] = v0.x; As[kq + 1][r0] = v0.y;
            As[kq + 2][r0] = v0.z; As[kq + 3][r0] = v0.w;
            As[kq + 0][r1] = v1.x; As[kq + 1][r1] = v1.y;
            As[kq + 2][r1] = v1.z; As[kq + 3][r1] = v1.w;
        }
        #pragma unroll
        for (int i = 0; i < 2; i++) {
            int lin = t + i * 256;
            int kk  = lin >> 5;
            int nq  = (lin & 31) * 4;
            *(float4*)&Bs[kk][nq] = *(const float4*)(Wx + (size_t)(k0 + kk) * NG + n0 + nq);
        }
        __syncthreads();
        #pragma unroll
        for (int kk = 0; kk < 16; kk++) {
            float a[8], b[8];
            *(float4*)&a[0] = *(const float4*)&As[kk][ty * 8];
            *(float4*)&a[4] = *(const float4*)&As[kk][ty * 8 + 4];
            *(float4*)&b[0] = *(const float4*)&Bs[kk][tx * 8];
            *(float4*)&b[4] = *(const float4*)&Bs[kk][tx * 8 + 4];
            #pragma unroll
            for (int i = 0; i < 8; i++)
                #pragma unroll
                for (int j = 0; j < 8; j++)
                    acc[i][j] += a[i] * b[j];
        }
        __syncthreads();
    }

    #pragma unroll
    for (int i = 0; i < 8; i++) {
        size_t m = (size_t)(m0 + ty * 8 + i);
        float* op = g_gx + m * NG + n0 + tx * 8;
        const float* bp = bias + n0 + tx * 8;
        #pragma unroll
        for (int j = 0; j < 8; j++) op[j] = acc[i][j] + bp[j];
    }
}

// ---------------- MMA macros (decoder-verified) ----------------
#define LDM_A(r0,r1,r2,r3,addr) \
    asm volatile("ldmatrix.sync.aligned.m8n8.x4.shared.b16 {%0,%1,%2,%3}, [%4];" \
        : "=r"(r0), "=r"(r1), "=r"(r2), "=r"(r3) : "r"(addr))

#define MMA_BF16(c, a, b) \
    asm volatile("mma.sync.aligned.m16n8k16.row.col.f32.bf16.bf16.f32 " \
        "{%0,%1,%2,%3}, {%4,%5,%6,%7}, {%8,%9}, {%0,%1,%2,%3};" \
        : "+f"((c)[0]), "+f"((c)[1]), "+f"((c)[2]), "+f"((c)[3]) \
        : "r"((a)[0]), "r"((a)[1]), "r"((a)[2]), "r"((a)[3]), "r"((b)[0]), "r"((b)[1]))

// ---------------- fused 2-layer LSTM recurrence (tensor-core core) ----------------
// 128 CTAs x 256 threads, 257 rounds. Round r: layer0 step r, layer1 step r-1.
// CTA owns 8 gate-cols. B tile (resident): stacked [W0(8); Wx1(8); Wh1(8); pad(8)]
// rows x 256 K, bf16 hi/lo, pitch 264. A tiles (per round): h1/h2 hi/lo, 32x256.
// 8 warps split K (32 each); fp32 partials reduced in smem; gate epilogue as round-4.
#define RPITCH 264                              // bf16 units per row
#define PLANE_B (32 * RPITCH * 2)               // 16896 bytes per bf16 plane
#define OFF_BHI 0
#define OFF_BLO PLANE_B
#define OFF_A   (2 * PLANE_B)                   // 4 A planes follow
#define OFF_PART (6 * PLANE_B)                  // fp32 partials [2][32][8][8]
#define RS_BYTES (OFF_PART + 2 * 32 * 8 * 8 * 4)   // 117,760 B

__global__ __launch_bounds__(256, 1) void fused_rnn(
    const float* __restrict__ Wh0,   // [256][1024]
    const float* __restrict__ Wx1,   // [256][1024]
    const float* __restrict__ Wh1,   // [256][1024]
    const float* __restrict__ b1,    // [1024]
    float*       __restrict__ h1_out,
    float*       __restrict__ h2_out)
{
    extern __shared__ char smc[];
    __nv_bfloat16* sBhi = (__nv_bfloat16*)(smc + OFF_BHI);
    __nv_bfloat16* sBlo = (__nv_bfloat16*)(smc + OFF_BLO);
    float*         sPart = (float*)(smc + OFF_PART);

    const int t    = threadIdx.x;
    const int warp = t >> 5;
    const int lane = t & 31;
    const int kg0  = blockIdx.x * 8;
    const int c    = t & 7;
    const int b    = t >> 3;
    const int k    = (kg0 + c) >> 2;
    const bool owner = (t & 3) == 0;
    const unsigned base = lane & ~3u;
    const unsigned grid = gridDim.x;

    // ---- load weight stack into smem (hi/lo split), resident for whole kernel ----
    for (int idx = t; idx < 3 * 8 * NH; idx += 256) {
        int m   = idx >> 11;          // 0=Wh0, 1=Wx1, 2=Wh1
        int rem = idx & 2047;
        int j   = rem >> 8;           // row within matrix (gate col)
        int kk  = rem & 255;
        const float* src = (m == 0) ? Wh0 : ((m == 1) ? Wx1 : Wh1);
        float x = src[(size_t)kk * NG + kg0 + j];
        __nv_bfloat16 hi = __float2bfloat16_rn(x);
        int row = m * 8 + j;
        sBhi[row * RPITCH + kk] = hi;
        sBlo[row * RPITCH + kk] = __float2bfloat16_rn(x - __bfloat162float(hi));
    }
    const float b1v = b1[kg0 + c];

    const uint32_t usm  = (uint32_t)__cvta_generic_to_shared(smc);
    const uint32_t uBhi = usm + OFF_BHI;
    const uint32_t uBlo = usm + OFF_BLO;
    const uint32_t uA0  = usm + OFF_A;              // h1hi
    const uint32_t uA1  = uA0 + PLANE_B;            // h1lo
    const uint32_t uA2  = uA1 + PLANE_B;            // h2hi
    const uint32_t uA3  = uA2 + PLANE_B;            // h2lo

    const int a_row = lane & 15;
    const int a_k   = (lane >> 4) * 8;
    const int b_row = (lane & 7) + ((lane >> 4) << 3);
    const int b_k   = ((lane >> 3) & 1) * 8;
    const int k0w   = warp * 32;

    float c1 = 0.f, c2 = 0.f;

    for (int r = 0; r <= SEQ; r++) {
        // prefetch gx (independent of barrier)
        int s0 = (r < SEQ) ? r : SEQ - 1;
        float gx0v = g_gx[(size_t)s0 * BATCH * NG + (size_t)b * NG + kg0 + c];

        // ---- wait for previous round's h publication (round-4 protocol) ----
        if (r > 0 && t == 0) {
            while (*(volatile unsigned*)&g_flag < (unsigned)r) { }
            __threadfence();
        }
        __syncthreads();

        // ---- refill A planes (bf16, parity r&1): 4 uint4 per plane per thread ----
        {
            const __nv_bfloat16* gp[4] = { g_h1hi[r & 1], g_h1lo[r & 1],
                                           g_h2hi[r & 1], g_h2lo[r & 1] };
            #pragma unroll
            for (int p = 0; p < 4; p++) {
                __nv_bfloat16* sAp = (__nv_bfloat16*)(smc + OFF_A + p * PLANE_B);
                #pragma unroll
                for (int i = 0; i < 4; i++) {
                    int cc = t + i * 256;            // 0..1023 (16B chunks)
                    int row = cc >> 5, c16 = cc & 31;
                    *(uint4*)&sAp[row * RPITCH + c16 * 8] =
                        __ldcg((const uint4*)(gp[p] + row * NH + c16 * 8));
                }
            }
        }
        __syncthreads();

        // ---- tensor-core z: warp handles K in [warp*32, warp*32+32) ----
        float z0a[2][4], z1a[2][4];
        #pragma unroll
        for (int m = 0; m < 2; m++)
            #pragma unroll
            for (int q = 0; q < 4; q++) { z0a[m][q] = 0.f; z1a[m][q] = 0.f; }

        #pragma unroll
        for (int kc = 0; kc < 2; kc++) {
            const int k0 = k0w + kc * 16;
            uint32_t ah1h[2][4], ah1l[2][4], ah2h[2][4], ah2l[2][4];
            #pragma unroll
            for (int m = 0; m < 2; m++) {
                uint32_t ro = (uint32_t)((m * 16 + a_row) * RPITCH + k0 + a_k) * 2;
                LDM_A(ah1h[m][0], ah1h[m][1], ah1h[m][2], ah1h[m][3], uA0 + ro);
                LDM_A(ah1l[m][0], ah1l[m][1], ah1l[m][2], ah1l[m][3], uA1 + ro);
                LDM_A(ah2h[m][0], ah2h[m][1], ah2h[m][2], ah2h[m][3], uA2 + ro);
                LDM_A(ah2l[m][0], ah2l[m][1], ah2l[m][2], ah2l[m][3], uA3 + ro);
            }
            uint32_t w0h[2], wxh[2], w1h[2], w0l[2], wxl[2], w1l[2];
            {
                uint32_t ro = (uint32_t)(b_row * RPITCH + k0 + b_k) * 2;       // rows 0-15
                uint32_t r0, r1, r2, r3;
                LDM_A(r0, r1, r2, r3, uBhi + ro);
                w0h[0] = r0; w0h[1] = r1; wxh[0] = r2; wxh[1] = r3;
                LDM_A(r0, r1, r2, r3, uBlo + ro);
                w0l[0] = r0; w0l[1] = r1; wxl[0] = r2; wxl[1] = r3;
                uint32_t ro2 = (uint32_t)((16 + b_row) * RPITCH + k0 + b_k) * 2; // rows 16-31
                LDM_A(r0, r1, r2, r3, uBhi + ro2);
                w1h[0] = r0; w1h[1] = r1;
                LDM_A(r0, r1, r2, r3, uBlo + ro2);
                w1l[0] = r0; w1l[1] = r1;
            }
            #pragma unroll
            for (int m = 0; m < 2; m++) {
                // z0 = h1 . W0  (split-bf16, 3 products)
                MMA_BF16(z0a[m], ah1h[m], w0h);
                MMA_BF16(z0a[m], ah1h[m], w0l);
                MMA_BF16(z0a[m], ah1l[m], w0h);
                // z1 = h1 . Wx1 + h2 . Wh1
                MMA_BF16(z1a[m], ah1h[m], wxh);
                MMA_BF16(z1a[m], ah1h[m], wxl);
                MMA_BF16(z1a[m], ah1l[m], wxh);
                MMA_BF16(z1a[m], ah2h[m], w1h);
                MMA_BF16(z1a[m], ah2h[m], w1l);
                MMA_BF16(z1a[m], ah2l[m], w1h);
            }
        }

        // ---- store per-warp partials: part[zt][row][col][warp] ----
        {
            const int g  = lane >> 2;
            const int t4 = lane & 3;
            #pragma unroll
            for (int m = 0; m < 2; m++) {
                int rowb = m * 16 + g;
                float* p0 = sPart + (0 * 32 + rowb) * 64 + (2 * t4) * 8 + warp;
                float* p1 = sPart + (1 * 32 + rowb) * 64 + (2 * t4) * 8 + warp;
                p0[0] = z0a[m][0]; p0[8] = z0a[m][1]; p0[512] = z0a[m][2]; p0[520] = z0a[m][3];
                p1[0] = z1a[m][0]; p1[8] = z1a[m][1]; p1[512] = z1a[m][2]; p1[520] = z1a[m][3];
            }
        }
        __syncthreads();

        // ---- reduce 8 K-partials; add gx / bias ----
        float z0 = gx0v, z1 = b1v;
        {
            const float* q0 = sPart + b * 64 + c * 8;
            const float* q1 = sPart + (32 + b) * 64 + c * 8;
            float4 v0 = *(const float4*)q0, v1 = *(const float4*)(q0 + 4);
            z0 += v0.x + v0.y + v0.z + v0.w + v1.x + v1.y + v1.z + v1.w;
            float4 u0 = *(const float4*)q1, u1 = *(const float4*)(q1 + 4);
            z1 += u0.x + u0.y + u0.z + u0.w + u1.x + u1.y + u1.z + u1.w;
        }

        // ---- gate gather + owner epilogue (round-4 pattern) ----
        float zi0 = __shfl_sync(0xffffffffu, z0, base + 0);
        float zf0 = __shfl_sync(0xffffffffu, z0, base + 1);
        float zo0 = __shfl_sync(0xffffffffu, z0, base + 2);
        float zg0 = __shfl_sync(0xffffffffu, z0, base + 3);
        float zi1 = __shfl_sync(0xffffffffu, z1, base + 0);
        float zf1 = __shfl_sync(0xffffffffu, z1, base + 1);
        float zo1 = __shfl_sync(0xffffffffu, z1, base + 2);
        float zg1 = __shfl_sync(0xffffffffu, z1, base + 3);

        if (owner) {
            int np = (r + 1) & 1;
            if (r < SEQ) {      // layer 0 step r
                float ig = 1.f / (1.f + __expf(-zi0));
                float fg = 1.f / (1.f + __expf(-zf0));
                float og = 1.f / (1.f + __expf(-zo0));
                float gg = tanhf(zg0);
                c1 = fg * c1 + ig * gg;
                float hn = og * tanhf(c1);
                __nv_bfloat16 hb = __float2bfloat16_rn(hn);
                g_h1hi[np][b * NH + k] = hb;
                g_h1lo[np][b * NH + k] = __float2bfloat16_rn(hn - __bfloat162float(hb));
                if (r == SEQ - 1) h1_out[b * NH + k] = hn;
            }
            if (r >= 1) {       // layer 1 step r-1
                int s1 = r - 1;
                float ig = 1.f / (1.f + __expf(-zi1));
                float fg = 1.f / (1.f + __expf(-zf1));
                float og = 1.f / (1.f + __expf(-zo1));
                float gg = tanhf(zg1);
                c2 = fg * c2 + ig * gg;
                float hn = og * tanhf(c2);
                __nv_bfloat16 hb = __float2bfloat16_rn(hn);
                __nv_bfloat16 lb = __float2bfloat16_rn(hn - __bfloat162float(hb));
                g_h2hi[np][b * NH + k] = hb;
                g_h2lo[np][b * NH + k] = lb;
                size_t m = (size_t)s1 * BATCH + b;
                g_Ahi[m * NH + k] = hb;
                g_Alo[m * NH + k] = lb;
                if (s1 == SEQ - 1) h2_out[b * NH + k] = hn;
            }
        }

        // ---- arrive (round-4 protocol, verbatim) ----
        if (r < SEQ) {
            __syncthreads();
            if (t == 0) {
                __threadfence();
                unsigned old = atomicAdd(&g_cnt, 1u);
                if (old == (unsigned)r * grid + grid - 1u)
                    atomicExch(&g_flag, (unsigned)(r + 1));
            }
        }
    }
}

// ---------------- bf16 split of decoder weights (scalar — proven) ----------------
__global__ __launch_bounds__(256) void conv_W(const float* __restrict__ W) {
    int i = blockIdx.x * blockDim.x + threadIdx.x;
    if (i < NVPAD * NH) {
        int v = i >> 8;
        float x = (v < NVOC) ? W[(size_t)v * NH + (i & 255)] : 0.f;
        __nv_bfloat16 hi = __float2bfloat16_rn(x);
        g_Whi[i] = hi;
        g_Wlo[i] = __float2bfloat16_rn(x - __bfloat162float(hi));
    }
}

// ---------------- tensor-core decoder GEMM (split-bf16; 2 CTAs/SM) ----------------
__global__ __launch_bounds__(256, 2) void gemm_dec_tc(
    const float* __restrict__ bias,
    float*       __restrict__ out)
{
    __shared__ __nv_bfloat16 sAhi[128][40];
    __shared__ __nv_bfloat16 sAlo[128][40];
    __shared__ __nv_bfloat16 sBhi[128][40];
    __shared__ __nv_bfloat16 sBlo[128][40];

    const int t    = threadIdx.x;
    const int warp = t >> 5;
    const int lane = t & 31;
    const int m0   = blockIdx.y * 128;
    const int n0   = blockIdx.x * 128;
    const int wm   = warp >> 2;
    const int wn   = warp & 3;

    float acc[4][4][4];
    #pragma unroll
    for (int i = 0; i < 4; i++)
        #pragma unroll
        for (int j = 0; j < 4; j++)
            #pragma unroll
            for (int q = 0; q < 4; q++) acc[i][j][q] = 0.f;

    const uint32_t bAhi = (uint32_t)__cvta_generic_to_shared(&sAhi[0][0]);
    const uint32_t bAlo = (uint32_t)__cvta_generic_to_shared(&sAlo[0][0]);
    const uint32_t bBhi = (uint32_t)__cvta_generic_to_shared(&sBhi[0][0]);
    const uint32_t bBlo = (uint32_t)__cvta_generic_to_shared(&sBlo[0][0]);

    const int a_row = (lane & 15);
    const int a_k   = (lane >> 4) * 8;
    const int b_row = (lane & 7) + ((lane >> 4) << 3);
    const int b_k   = ((lane >> 3) & 1) * 8;

    for (int kc = 0; kc < 8; kc++) {
        const int k0 = kc * 32;
        #pragma unroll
        for (int h = 0; h < 2; h++) {
            int cc  = t + h * 256;
            int row = cc >> 2;
            int q   = cc & 3;
            size_t gA = (size_t)(m0 + row) * NH + k0 + q * 8;
            size_t gB = (size_t)(n0 + row) * NH + k0 + q * 8;
            *(uint4*)&sAhi[row][q * 8] = *(const uint4*)(g_Ahi + gA);
            *(uint4*)&sAlo[row][q * 8] = *(const uint4*)(g_Alo + gA);
            *(uint4*)&sBhi[row][q * 8] = *(const uint4*)(g_Whi + gB);
            *(uint4*)&sBlo[row][q * 8] = *(const uint4*)(g_Wlo + gB);
        }
        __syncthreads();

        #pragma unroll
        for (int ks = 0; ks < 32; ks += 16) {
            uint32_t af[4][4];
            uint32_t bh[4][2], bl[4][2];

            #pragma unroll
            for (int nh = 0; nh < 2; nh++) {
                int roff = (wn * 32 + nh * 16 + b_row) * 40 + ks + b_k;
                uint32_t r0, r1, r2, r3;
                LDM_A(r0, r1, r2, r3, bBhi + roff * 2);
                bh[2*nh][0] = r0; bh[2*nh][1] = r1;
                bh[2*nh+1][0] = r2; bh[2*nh+1][1] = r3;
                LDM_A(r0, r1, r2, r3, bBlo + roff * 2);
                bl[2*nh][0] = r0; bl[2*nh][1] = r1;
                bl[2*nh+1][0] = r2; bl[2*nh+1][1] = r3;
            }
            #pragma unroll
            for (int mi = 0; mi < 4; mi++) {
                int roff = (wm * 64 + mi * 16 + a_row) * 40 + ks + a_k;
                LDM_A(af[mi][0], af[mi][1], af[mi][2], af[mi][3], bAhi + roff * 2);
            }
            #pragma unroll
            for (int mi = 0; mi < 4; mi++)
                #pragma unroll
                for (int ni = 0; ni < 4; ni++) {
                    MMA_BF16(acc[mi][ni], af[mi], bh[ni]);
                    MMA_BF16(acc[mi][ni], af[mi], bl[ni]);
                }
            #pragma unroll
            for (int mi = 0; mi < 4; mi++) {
                int roff = (wm * 64 + mi * 16 + a_row) * 40 + ks + a_k;
                LDM_A(af[mi][0], af[mi][1], af[mi][2], af[mi][3], bAlo + roff * 2);
            }
            #pragma unroll
            for (int mi = 0; mi < 4; mi++)
                #pragma unroll
                for (int ni = 0; ni < 4; ni++)
                    MMA_BF16(acc[mi][ni], af[mi], bh[ni]);
        }
        __syncthreads();
    }

    const int g  = lane >> 2;
    const int t4 = lane & 3;
    #pragma unroll
    for (int mi = 0; mi < 4; mi++) {
        #pragma unroll
        for (int ni = 0; ni < 4; ni++) {
            int col = n0 + wn * 32 + ni * 8 + t4 * 2;
            if (col < NVOC) {
                float b0 = bias[col], b1 = bias[col + 1];
                int row0 = m0 + wm * 64 + mi * 16 + g;
                float2 v0 = make_float2(acc[mi][ni][0] + b0, acc[mi][ni][1] + b1);
                float2 v1 = make_float2(acc[mi][ni][2] + b0, acc[mi][ni][3] + b1);
                *(float2*)(out + (size_t)row0 * NVOC + col) = v0;
                *(float2*)(out + (size_t)(row0 + 8) * NVOC + col) = v1;
            }
        }
    }
}

// ---------------- launch ----------------
extern "C" void kernel_launch(void* const* d_in, const int* in_sizes, int n_in,
                              void* d_out, int out_size) {
    const int*   tokens  = (const int*)  d_in[0];
    const float* embed_W = (const float*)d_in[1];
    const float* Wx0     = (const float*)d_in[2];
    const float* Wh0     = (const float*)d_in[3];
    const float* b0      = (const float*)d_in[4];
    const float* Wx1     = (const float*)d_in[5];
    const float* Wh1     = (const float*)d_in[6];
    const float* b1      = (const float*)d_in[7];
    const float* dec_W   = (const float*)d_in[8];
    const float* dec_b   = (const float*)d_in[9];
    (void)in_sizes; (void)n_in;

    float* out    = (float*)d_out;
    float* h1_out = out + (size_t)out_size - 2 * BATCH * NH;
    float* h2_out = out + (size_t)out_size - 1 * BATCH * NH;

    static bool attr_done = false;
    if (!attr_done) {
        cudaFuncSetAttribute(fused_rnn, cudaFuncAttributeMaxDynamicSharedMemorySize, RS_BYTES);
        attr_done = true;
    }

    conv_W<<<(NVPAD * NH + 255) / 256, 256>>>(dec_W);
    init_state<<<16, 256>>>();
    gemm_gx<<<dim3(8, 64), 256>>>(embed_W, tokens, Wx0, b0);
    fused_rnn<<<128, 256, RS_BYTES>>>(Wh0, Wx1, Wh1, b1, h1_out, h2_out);
    gemm_dec_tc<<<dim3(79, 64), 256>>>(dec_b, out);
}